// round 16
// baseline (speedup 1.0000x reference)
#include <cuda_runtime.h>
#include <cuda_bf16.h>
#include <cuda_fp16.h>
#include <cstdint>

#define NQ 8192
#define NK 8192
#define HD 128
#define BM 128
#define BN 64
#define NQT (NQ / BM)               // 64 q-tiles
#define NKT (NK / BN)               // 128 k-tiles per q-tile
#define NJOBS (NQT * NKT)           // 8192
#define CHUNK 56
#define NCTAS ((NJOBS + CHUNK - 1) / CHUNK)   // 147
#define THREADS 256
#define PITCH 136   // padded row pitch in 16-bit elements (272B: conflict-free ldmatrix)
#define NEG_INF (-3.402823466e38f)

// smem element offsets (16-bit units)
#define QHI_E 0
#define QLO_E 17408                 // 128*PITCH
#define BUFBASE_E 34816
#define BUFSZ_E 26112               // per KV buffer: KHI(8704) KLO(8704) VHI(8704)
// within a KV buffer (bytes): KHI +0, KLO +17408, VHI +34816
#define SMEM_BYTES ((BUFBASE_E + 3 * BUFSZ_E) * 2)   // 226304 B

// pre-split operands + per-CTA-segment partials (static device memory)
__device__ __nv_bfloat16 gQhi[NQ * HD], gQlo[NQ * HD];
__device__ __nv_bfloat16 gKhi[NK * HD], gKlo[NK * HD];
__device__ __half gVhi[NK * HD];
__device__ float gP[2 * (NCTAS + 1) * BM * HD];   // [slot][128][128]
__device__ float gLp[2 * (NCTAS + 1) * BM];       // [slot][128]
__device__ float gMp[2 * (NCTAS + 1) * BM];       // [slot][128] row maxes

// ---------------- helpers ----------------
__device__ __forceinline__ uint32_t smem_u32(const void* p) {
    uint32_t a;
    asm("{ .reg .u64 t; cvta.to.shared.u64 t, %1; cvt.u32.u64 %0, t; }" : "=r"(a) : "l"(p));
    return a;
}
__device__ __forceinline__ void ldsm4(uint32_t* r, uint32_t a) {
    asm volatile("ldmatrix.sync.aligned.m8n8.x4.shared.b16 {%0,%1,%2,%3}, [%4];"
                 : "=r"(r[0]), "=r"(r[1]), "=r"(r[2]), "=r"(r[3]) : "r"(a));
}
__device__ __forceinline__ void ldsm4t(uint32_t* r, uint32_t a) {
    asm volatile("ldmatrix.sync.aligned.m8n8.x4.trans.shared.b16 {%0,%1,%2,%3}, [%4];"
                 : "=r"(r[0]), "=r"(r[1]), "=r"(r[2]), "=r"(r[3]) : "r"(a));
}
// non-volatile: pure register computation; dataflow orders it
__device__ __forceinline__ void mma16816(float* d, const uint32_t* a, const uint32_t* b) {
    asm("mma.sync.aligned.m16n8k16.row.col.f32.bf16.bf16.f32 "
        "{%0,%1,%2,%3}, {%4,%5,%6,%7}, {%8,%9}, {%0,%1,%2,%3};"
        : "+f"(d[0]), "+f"(d[1]), "+f"(d[2]), "+f"(d[3])
        : "r"(a[0]), "r"(a[1]), "r"(a[2]), "r"(a[3]), "r"(b[0]), "r"(b[1]));
}
__device__ __forceinline__ void mma16816f(float* d, const uint32_t* a, const uint32_t* b) {
    asm("mma.sync.aligned.m16n8k16.row.col.f32.f16.f16.f32 "
        "{%0,%1,%2,%3}, {%4,%5,%6,%7}, {%8,%9}, {%0,%1,%2,%3};"
        : "+f"(d[0]), "+f"(d[1]), "+f"(d[2]), "+f"(d[3])
        : "r"(a[0]), "r"(a[1]), "r"(a[2]), "r"(a[3]), "r"(b[0]), "r"(b[1]));
}
__device__ __forceinline__ uint32_t u32h2(float lo, float hi) {
    __half2 v = __floats2half2_rn(lo, hi);     // .x = lo (low 16 bits)
    return *reinterpret_cast<uint32_t*>(&v);
}
#define CPASYNC(dst, src) \
    asm volatile("cp.async.cg.shared.global [%0], [%1], 16;" :: "r"(dst), "l"(src))
#define CP_COMMIT() asm volatile("cp.async.commit_group;" ::: "memory")
#define CP_WAIT0()  asm volatile("cp.async.wait_group 0;" ::: "memory")
#define CP_WAIT1()  asm volatile("cp.async.wait_group 1;" ::: "memory")

__device__ __forceinline__ void load_kv_tile(uint32_t sb, uint32_t bufE, int n0, int tid) {
#pragma unroll
    for (int i = 0; i < 4; i++) {
        int f = i * THREADS + tid;
        int row = f >> 4, ch = f & 15;
        size_t g = (size_t)(n0 + row) * HD + ch * 8;
        uint32_t d = sb + (bufE + (uint32_t)(row * PITCH + ch * 8)) * 2;
        CPASYNC(d,         gKhi + g);
        CPASYNC(d + 17408, gKlo + g);
        CPASYNC(d + 34816, gVhi + g);
    }
}

// GEMM1 for one tile: s = Qhi*Khi + Qhi*Klo + Qlo*Khi (bf16 3-term)
__device__ __forceinline__ void gemm1_tile(
    float s[8][4], uint32_t sb, uint32_t bufbyte,
    const uint32_t qfh[8][4], const uint32_t qfl[8][4],
    int krow, int kkoff)
{
#pragma unroll
    for (int i = 0; i < 8; i++)
#pragma unroll
        for (int jj = 0; jj < 4; jj++) s[i][jj] = 0.0f;

#pragma unroll
    for (int kb = 0; kb < 8; kb++) {
#pragma unroll
        for (int hpair = 0; hpair < 2; hpair++) {
            uint32_t bh0[4], bl0[4], bh1[4], bl1[4];
            uint32_t ba0 = sb + bufbyte +
                (uint32_t)(((2 * hpair) * 16 + krow) * PITCH + kb * 16 + kkoff) * 2;
            uint32_t ba1 = sb + bufbyte +
                (uint32_t)(((2 * hpair + 1) * 16 + krow) * PITCH + kb * 16 + kkoff) * 2;
            ldsm4(bh0, ba0);
            ldsm4(bl0, ba0 + 17408);
            ldsm4(bh1, ba1);
            ldsm4(bl1, ba1 + 17408);
            float* s0 = s[4 * hpair + 0];
            float* s1 = s[4 * hpair + 1];
            float* s2 = s[4 * hpair + 2];
            float* s3 = s[4 * hpair + 3];
            mma16816(s0, qfh[kb], &bh0[0]);
            mma16816(s1, qfh[kb], &bh0[2]);
            mma16816(s2, qfh[kb], &bh1[0]);
            mma16816(s3, qfh[kb], &bh1[2]);
            mma16816(s0, qfh[kb], &bl0[0]);
            mma16816(s1, qfh[kb], &bl0[2]);
            mma16816(s2, qfh[kb], &bl1[0]);
            mma16816(s3, qfh[kb], &bl1[2]);
            mma16816(s0, qfl[kb], &bh0[0]);
            mma16816(s1, qfl[kb], &bh0[2]);
            mma16816(s2, qfl[kb], &bh1[0]);
            mma16816(s3, qfl[kb], &bh1[2]);
        }
    }
}

// ---------------- prep: Q,K -> bf16 hi/lo; V -> fp16 ----------------
__global__ void prep_kernel(const float* __restrict__ Q, const float* __restrict__ K,
                            const float* __restrict__ V) {
    int i = blockIdx.x * blockDim.x + threadIdx.x;      // one float4 per tensor
    if (i >= NQ * HD / 4) return;
    const float4 q = ((const float4*)Q)[i];
    const float4 k = ((const float4*)K)[i];
    const float4 v = ((const float4*)V)[i];
    float xq[4] = {q.x, q.y, q.z, q.w};
    float xk[4] = {k.x, k.y, k.z, k.w};
    __nv_bfloat16 qh[4], ql[4], kh[4], kl[4];
#pragma unroll
    for (int j = 0; j < 4; j++) {
        qh[j] = __float2bfloat16(xq[j]);
        ql[j] = __float2bfloat16(xq[j] - __bfloat162float(qh[j]));
        kh[j] = __float2bfloat16(xk[j]);
        kl[j] = __float2bfloat16(xk[j] - __bfloat162float(kh[j]));
    }
    ((__nv_bfloat162*)gQhi)[2 * i]     = __halves2bfloat162(qh[0], qh[1]);
    ((__nv_bfloat162*)gQhi)[2 * i + 1] = __halves2bfloat162(qh[2], qh[3]);
    ((__nv_bfloat162*)gQlo)[2 * i]     = __halves2bfloat162(ql[0], ql[1]);
    ((__nv_bfloat162*)gQlo)[2 * i + 1] = __halves2bfloat162(ql[2], ql[3]);
    ((__nv_bfloat162*)gKhi)[2 * i]     = __halves2bfloat162(kh[0], kh[1]);
    ((__nv_bfloat162*)gKhi)[2 * i + 1] = __halves2bfloat162(kh[2], kh[3]);
    ((__nv_bfloat162*)gKlo)[2 * i]     = __halves2bfloat162(kl[0], kl[1]);
    ((__nv_bfloat162*)gKlo)[2 * i + 1] = __halves2bfloat162(kl[2], kl[3]);
    ((__half2*)gVhi)[2 * i]     = __floats2half2_rn(v.x, v.y);
    ((__half2*)gVhi)[2 * i + 1] = __floats2half2_rn(v.z, v.w);
}

// ---------------- main attention kernel (persistent, cross-tile pipelined) ----------------
__global__ void __launch_bounds__(THREADS, 1)
attn_mma_kernel()
{
    extern __shared__ __nv_bfloat16 sm[];
    const uint32_t sb = smem_u32(sm);
    const int tid  = threadIdx.x;
    const int wid  = tid >> 5;
    const int lane = tid & 31;
    const int cta  = blockIdx.x;

    const int job0 = cta * CHUNK;
    const int job1 = min(job0 + CHUNK, NJOBS);
    if (job0 >= job1) return;

    // buffer byte offsets for j mod 3
    auto bufbyteof = [&](int j) -> uint32_t {
        return (uint32_t)(BUFBASE_E + (j % 3) * BUFSZ_E) * 2;
    };
    auto bufelemof = [&](int j) -> uint32_t {
        return (uint32_t)(BUFBASE_E + (j % 3) * BUFSZ_E);
    };

    // prologue: prefetch first two KV tiles
    load_kv_tile(sb, bufelemof(job0), (job0 & (NKT - 1)) * BN, tid);
    CP_COMMIT();
    if (job0 + 1 < job1) {
        load_kv_tile(sb, bufelemof(job0 + 1), ((job0 + 1) & (NKT - 1)) * BN, tid);
        CP_COMMIT();
    }

    // ldmatrix address components
    const int qrow  = wid * 16 + (lane & 7) + 8 * ((lane >> 3) & 1);
    const uint32_t aQbase = sb + (uint32_t)(QHI_E + qrow * PITCH + 8 * (lane >> 4)) * 2;
    const int krow  = (lane & 7) + 8 * (lane >> 4);       // + nbp*16
    const int kkoff = 8 * ((lane >> 3) & 1);              // + kb*16
    const int vrow  = (lane & 7) + 8 * ((lane >> 3) & 1); // + kb*16
    const int vcol  = 8 * (lane >> 4);                    // + nbp*16

    const int qt0 = job0 >> 7;
    int j = job0;
    while (j < job1) {
        const int qt = j >> 7;
        const int segend = min(job1, (qt + 1) << 7);
        const int q0 = qt * BM;

        // protect Q smem from previous segment's readers
        __syncthreads();
#pragma unroll
        for (int i = 0; i < 8; i++) {
            int f = i * THREADS + tid;
            int row = f >> 4, ch = f & 15;
            size_t g = (size_t)(q0 + row) * HD + ch * 8;
            uint4 h = *(const uint4*)(gQhi + g);
            uint4 l = *(const uint4*)(gQlo + g);
            *(uint4*)(sm + QHI_E + row * PITCH + ch * 8) = h;
            *(uint4*)(sm + QLO_E + row * PITCH + ch * 8) = l;
        }
        CP_WAIT1();        // ensure buf[j] landed (first segment); later segments: no-op
        __syncthreads();   // Q + buf[j] visible

        // Q fragments register-resident for the whole segment
        uint32_t qfh[8][4], qfl[8][4];
#pragma unroll
        for (int kb = 0; kb < 8; kb++) {
            uint32_t aaddr = aQbase + kb * 32;
            ldsm4(qfh[kb], aaddr);
            ldsm4(qfl[kb], aaddr + QLO_E * 2);
        }

        float o[16][4];
#pragma unroll
        for (int i = 0; i < 16; i++)
#pragma unroll
            for (int jj = 0; jj < 4; jj++) o[i][jj] = 0.0f;
        float lsum0 = 0.0f, lsum1 = 0.0f;
        float m0 = NEG_INF, m1 = NEG_INF;

        // scores for first tile of segment
        float s[8][4];
        gemm1_tile(s, sb, bufbyteof(j), qfh, qfl, krow, kkoff);

        for (; j < segend; j++) {
            const uint32_t bufcur = bufbyteof(j);

            if (j + 1 < job1) CP_WAIT0();   // cp(j+1) landed
            __syncthreads();                // visibility + all warps done with buf[(j+2)%3]
            if (j + 2 < job1) {
                load_kv_tile(sb, bufelemof(j + 2), ((j + 2) & (NKT - 1)) * BN, tid);
                CP_COMMIT();
            }

            // ---- softmax(j): tree max, rescale o, phi + lsum (MUFU/ALU) ----
            float t0[8], t1[8];
#pragma unroll
            for (int nb = 0; nb < 8; nb++) {
                t0[nb] = fmaxf(s[nb][0], s[nb][1]);
                t1[nb] = fmaxf(s[nb][2], s[nb][3]);
            }
            float mx0 = fmaxf(fmaxf(fmaxf(t0[0], t0[1]), fmaxf(t0[2], t0[3])),
                              fmaxf(fmaxf(t0[4], t0[5]), fmaxf(t0[6], t0[7])));
            float mx1 = fmaxf(fmaxf(fmaxf(t1[0], t1[1]), fmaxf(t1[2], t1[3])),
                              fmaxf(fmaxf(t1[4], t1[5]), fmaxf(t1[6], t1[7])));
            mx0 = fmaxf(mx0, __shfl_xor_sync(0xffffffffu, mx0, 1));
            mx0 = fmaxf(mx0, __shfl_xor_sync(0xffffffffu, mx0, 2));
            mx1 = fmaxf(mx1, __shfl_xor_sync(0xffffffffu, mx1, 1));
            mx1 = fmaxf(mx1, __shfl_xor_sync(0xffffffffu, mx1, 2));
            const float mn0 = fmaxf(m0, mx0);
            const float mn1 = fmaxf(m1, mx1);
            const float a0 = __expf(m0 - mn0);   // 0 on first tile (m=-inf)
            const float a1 = __expf(m1 - mn1);
            m0 = mn0; m1 = mn1;
            lsum0 *= a0; lsum1 *= a1;
#pragma unroll
            for (int i = 0; i < 16; i++) {
                o[i][0] *= a0; o[i][1] *= a0;
                o[i][2] *= a1; o[i][3] *= a1;
            }

            uint32_t phia[4][4];
#pragma unroll
            for (int kb = 0; kb < 4; kb++) {
#pragma unroll
                for (int half = 0; half < 2; half++) {
                    const int nb = 2 * kb + half;
                    float e0 = __expf(s[nb][0] - mn0);
                    float e1 = __expf(s[nb][1] - mn0);
                    float e2 = __expf(s[nb][2] - mn1);
                    float e3 = __expf(s[nb][3] - mn1);
                    uint32_t p01 = u32h2(e0, e1);
                    uint32_t p23 = u32h2(e2, e3);
                    phia[kb][2 * half]     = p01;
                    phia[kb][2 * half + 1] = p23;
                    // denominator from the SAME fp16-rounded weights (consistency)
                    float2 f01 = __half22float2(*reinterpret_cast<__half2*>(&p01));
                    float2 f23 = __half22float2(*reinterpret_cast<__half2*>(&p23));
                    lsum0 += f01.x + f01.y;
                    lsum1 += f23.x + f23.y;
                }
            }

            // ---- GEMM1(j+1): independent of softmax — runs under it on tensor ----
            float s_next[8][4];
            const bool have_next = (j + 1 < segend);
            if (have_next)
                gemm1_tile(s_next, sb, bufbyteof(j + 1), qfh, qfl, krow, kkoff);

            // ---- GEMM2(j): O += Phi*Vhi (fp16 1-term) ----
#pragma unroll
            for (int kb = 0; kb < 4; kb++) {
#pragma unroll
                for (int hp = 0; hp < 4; hp++) {
                    uint32_t bh0[4], bh1[4];
                    uint32_t va0 = sb + bufcur + 34816 +
                        (uint32_t)((kb * 16 + vrow) * PITCH + (2 * hp) * 16 + vcol) * 2;
                    ldsm4t(bh0, va0);
                    ldsm4t(bh1, va0 + 32);
                    mma16816f(o[4 * hp + 0], phia[kb], &bh0[0]);
                    mma16816f(o[4 * hp + 1], phia[kb], &bh0[2]);
                    mma16816f(o[4 * hp + 2], phia[kb], &bh1[0]);
                    mma16816f(o[4 * hp + 3], phia[kb], &bh1[2]);
                }
            }

            if (have_next) {
#pragma unroll
                for (int i = 0; i < 8; i++)
#pragma unroll
                    for (int jj = 0; jj < 4; jj++) s[i][jj] = s_next[i][jj];
            }
        }

        // ---- segment epilogue: partial numerator + row sums + row maxes ----
        float ls0 = lsum0 + __shfl_xor_sync(0xffffffffu, lsum0, 1);
        ls0 += __shfl_xor_sync(0xffffffffu, ls0, 2);
        float ls1 = lsum1 + __shfl_xor_sync(0xffffffffu, lsum1, 1);
        ls1 += __shfl_xor_sync(0xffffffffu, ls1, 2);

        const int seg = (qt == qt0) ? 0 : 1;
        const int slot = 2 * cta + seg;
        float* base = gP + (size_t)slot * (BM * HD);
        const int r0l = wid * 16 + (lane >> 2);
        const int r1l = r0l + 8;
        if ((lane & 3) == 0) {
            gLp[slot * BM + r0l] = ls0;
            gLp[slot * BM + r1l] = ls1;
            gMp[slot * BM + r0l] = m0;
            gMp[slot * BM + r1l] = m1;
        }
#pragma unroll
        for (int nb = 0; nb < 16; nb++) {
            int col = nb * 8 + 2 * (lane & 3);
            *(float2*)(base + (size_t)r0l * HD + col) = make_float2(o[nb][0], o[nb][1]);
            *(float2*)(base + (size_t)r1l * HD + col) = make_float2(o[nb][2], o[nb][3]);
        }
    }
}

// ---------------- combine partial slots (max-merge) ----------------
__global__ void combine_kernel(float* __restrict__ O) {
    int idx = blockIdx.x * blockDim.x + threadIdx.x;   // one float4 per thread
    if (idx >= NQ * (HD / 4)) return;
    const int r  = idx >> 5;
    const int c4 = (idx & 31) * 4;
    const int q  = r >> 7;           // q-tile
    const int rl = r & 127;          // row within tile
    const int c0 = (q << 7) / CHUNK;
    const int c1 = ((q << 7) + 127) / CHUNK;

    float M = NEG_INF;
    for (int c = c0; c <= c1; c++) {
        int seg = (((c * CHUNK) >> 7) == q) ? 0 : 1;
        M = fmaxf(M, gMp[(2 * c + seg) * BM + rl]);
    }
    float4 acc = make_float4(0.f, 0.f, 0.f, 0.f);
    float l = 0.0f;
    for (int c = c0; c <= c1; c++) {
        int seg = (((c * CHUNK) >> 7) == q) ? 0 : 1;
        int slot = 2 * c + seg;
        float w = __expf(gMp[slot * BM + rl] - M);
        const float* p = gP + (size_t)slot * (BM * HD) + (size_t)rl * HD + c4;
        float4 v = *(const float4*)p;
        acc.x += v.x * w; acc.y += v.y * w; acc.z += v.z * w; acc.w += v.w * w;
        l += gLp[slot * BM + rl] * w;
    }
    float inv = 1.0f / l;
    *(float4*)(O + (size_t)r * HD + c4) =
        make_float4(acc.x * inv, acc.y * inv, acc.z * inv, acc.w * inv);
}

extern "C" void kernel_launch(void* const* d_in, const int* in_sizes, int n_in,
                              void* d_out, int out_size)
{
    const float* Q = (const float*)d_in[0];
    const float* K = (const float*)d_in[1];
    const float* V = (const float*)d_in[2];
    float* O = (float*)d_out;

    cudaFuncSetAttribute(attn_mma_kernel,
                         cudaFuncAttributeMaxDynamicSharedMemorySize, SMEM_BYTES);

    prep_kernel<<<(NQ * HD / 4 + 255) / 256, 256>>>(Q, K, V);
    attn_mma_kernel<<<NCTAS, THREADS, SMEM_BYTES>>>();
    combine_kernel<<<(NQ * (HD / 4) + 255) / 256, 256>>>(O);
}